// round 11
// baseline (speedup 1.0000x reference)
#include <cuda_runtime.h>
#include <cuda_bf16.h>
#include <cstdint>

#define T_STEPS 512
#define HID 64
#define NB 16         // batches per CTA: group P = 0-7, group Q = 8-15
#define KPAD 72       // bf16 per h-row: 144B = 36 words -> bank+4 per row (conflict-free)

__device__ __forceinline__ float tanh_fast(float x) {
    float e; asm("ex2.approx.f32 %0, %1;" : "=f"(e) : "f"(x * 2.885390082f)); // 2*log2(e)
    float r; asm("rcp.approx.f32 %0, %1;" : "=f"(r) : "f"(e + 1.0f));
    return fmaf(-2.0f, r, 1.0f);
}

__device__ __forceinline__ void split2(float a, float b, uint32_t &uhi, uint32_t &ulo) {
    __nv_bfloat16 ah = __float2bfloat16_rn(a), bh = __float2bfloat16_rn(b);
    float ar = a - __bfloat162float(ah), br = b - __bfloat162float(bh);
    __nv_bfloat16 al = __float2bfloat16_rn(ar), bl = __float2bfloat16_rn(br);
    uhi = ((uint32_t)__bfloat16_as_ushort(bh) << 16) | __bfloat16_as_ushort(ah);
    ulo = ((uint32_t)__bfloat16_as_ushort(bl) << 16) | __bfloat16_as_ushort(al);
}

// Ampere-style bf16 MMA, fp32 accumulate: arch-neutral PTX (works on plain sm_103).
__device__ __forceinline__ void mma16816(float d[4], const uint32_t a[4], uint32_t b0, uint32_t b1) {
    asm volatile("mma.sync.aligned.m16n8k16.row.col.f32.bf16.bf16.f32 "
        "{%0,%1,%2,%3}, {%4,%5,%6,%7}, {%8,%9}, {%0,%1,%2,%3};"
        : "+f"(d[0]), "+f"(d[1]), "+f"(d[2]), "+f"(d[3])
        : "r"(a[0]), "r"(a[1]), "r"(a[2]), "r"(a[3]), "r"(b0), "r"(b1));
}

// Split named barriers: 128 arrives + 128 syncs = 256 per phase.
#define BAR_ARRIVE(id) asm volatile("bar.arrive " #id ", 256;" ::: "memory")
#define BAR_SYNC(id)   asm volatile("bar.sync "   #id ", 256;" ::: "memory")

// CTA: 4 warps, 16 batches in two independent groups P/Q, software-pipelined so each
// group's MMA latency + barrier wait hides under the other group's work. grid=128 -> 1 CTA/SM.
__global__ void __launch_bounds__(128)
rnn_hmma2_kernel(const float* __restrict__ x,
                 const float* __restrict__ W_ih,
                 const float* __restrict__ W_hh,
                 const float* __restrict__ b_ih,
                 const float* __restrict__ b_hh,
                 const float* __restrict__ fc_w,
                 const float* __restrict__ fc_b,
                 float* __restrict__ out)
{
    __shared__ __align__(16) float sx[T_STEPS][NB];                    // x transposed, 32KB
    __shared__ __align__(16) __nv_bfloat16 hbuf[2][2][2][8][KPAD];     // [grp][pp][hi/lo][n][k]
    __shared__ float red[4][NB];

    const int tid  = threadIdx.x;
    const int lane = tid & 31, wid = tid >> 5;
    const int g = lane >> 2, q = lane & 3;
    const int r0 = wid * 16 + g, r1 = r0 + 8;    // this thread's two M rows
    const int c0 = 2 * q, c1 = 2 * q + 1;        // batch cols within a group
    const int b0 = blockIdx.x * NB;

    // ---- loop-invariant A fragments: W_hh rows r0/r1, hi+lo bf16 splits (32 regs) ----
    uint32_t Ahi[4][4], Alo[4][4];
#pragma unroll
    for (int kt = 0; kt < 4; ++kt) {
        int kb = kt * 16 + 2 * q;
        split2(W_hh[r0 * HID + kb],     W_hh[r0 * HID + kb + 1], Ahi[kt][0], Alo[kt][0]);
        split2(W_hh[r1 * HID + kb],     W_hh[r1 * HID + kb + 1], Ahi[kt][1], Alo[kt][1]);
        split2(W_hh[r0 * HID + kb + 8], W_hh[r0 * HID + kb + 9], Ahi[kt][2], Alo[kt][2]);
        split2(W_hh[r1 * HID + kb + 8], W_hh[r1 * HID + kb + 9], Ahi[kt][3], Alo[kt][3]);
    }

    const float wih0 = W_ih[r0],            wih1 = W_ih[r1];
    const float bi0  = b_ih[r0] + b_hh[r0], bi1  = b_ih[r1] + b_hh[r1];
    const float fw0  = fc_w[r0],            fw1  = fc_w[r1];

    // ---- stage x transposed: sx[t][n] ----
    {
        const float4* xg = reinterpret_cast<const float4*>(x + (size_t)b0 * T_STEPS);
        for (int i = tid; i < NB * (T_STEPS / 4); i += 128) {
            int bb = i >> 7, t4 = (i & 127) * 4;
            float4 v = xg[(i >> 7) * 128 + (i & 127)];
            sx[t4 + 0][bb] = v.x; sx[t4 + 1][bb] = v.y;
            sx[t4 + 2][bb] = v.z; sx[t4 + 3][bb] = v.w;
        }
    }
    __syncthreads();

    auto store_h = [&](int grp, int pp, const float hv[4]) {
        const int nn[4] = {c0, c1, c0, c1};
        const int mm[4] = {r0, r0, r1, r1};
#pragma unroll
        for (int i = 0; i < 4; ++i) {
            __nv_bfloat16 vhi = __float2bfloat16_rn(hv[i]);
            __nv_bfloat16 vlo = __float2bfloat16_rn(hv[i] - __bfloat162float(vhi));
            hbuf[grp][pp][0][nn[i]][mm[i]] = vhi;
            hbuf[grp][pp][1][nn[i]][mm[i]] = vlo;
        }
    };
    auto load_b = [&](int grp, int pp, uint32_t Bhi[4][2], uint32_t Blo[4][2]) {
#pragma unroll
        for (int kt = 0; kt < 4; ++kt) {
            int kb = kt * 16 + 2 * q;
            Bhi[kt][0] = *reinterpret_cast<const uint32_t*>(&hbuf[grp][pp][0][g][kb]);
            Bhi[kt][1] = *reinterpret_cast<const uint32_t*>(&hbuf[grp][pp][0][g][kb + 8]);
            Blo[kt][0] = *reinterpret_cast<const uint32_t*>(&hbuf[grp][pp][1][g][kb]);
            Blo[kt][1] = *reinterpret_cast<const uint32_t*>(&hbuf[grp][pp][1][g][kb + 8]);
        }
    };
    auto do_mma = [&](float dA[4], float dB[4], float dC[4],
                      uint32_t Bhi[4][2], uint32_t Blo[4][2]) {
#pragma unroll
        for (int kt = 0; kt < 4; ++kt) {
            mma16816(dA, Ahi[kt], Bhi[kt][0], Bhi[kt][1]);   // Whi * h_hi
            mma16816(dB, Ahi[kt], Blo[kt][0], Blo[kt][1]);   // Whi * h_lo
            mma16816(dC, Alo[kt], Bhi[kt][0], Bhi[kt][1]);   // Wlo * h_hi
        }
    };

    // ---- t=0: h(0)=tanh(x W_ih + bias) for both groups -> pp0, arrive ----
    float hp[4], hq[4];
    {
        float2 xp = *reinterpret_cast<const float2*>(&sx[0][c0]);
        float2 xq = *reinterpret_cast<const float2*>(&sx[0][c0 + 8]);
        hp[0] = tanh_fast(fmaf(wih0, xp.x, bi0)); hp[1] = tanh_fast(fmaf(wih0, xp.y, bi0));
        hp[2] = tanh_fast(fmaf(wih1, xp.x, bi1)); hp[3] = tanh_fast(fmaf(wih1, xp.y, bi1));
        hq[0] = tanh_fast(fmaf(wih0, xq.x, bi0)); hq[1] = tanh_fast(fmaf(wih0, xq.y, bi0));
        hq[2] = tanh_fast(fmaf(wih1, xq.x, bi1)); hq[3] = tanh_fast(fmaf(wih1, xq.y, bi1));
    }
    store_h(0, 0, hp); BAR_ARRIVE(1);
    store_h(1, 0, hq); BAR_ARRIVE(2);

    // ---- preloop: P step 1 MMA in flight ----
    float dPA[4] = {0,0,0,0}, dPB[4] = {0,0,0,0}, dPC[4] = {0,0,0,0};
    {
        uint32_t Bhi[4][2], Blo[4][2];
        BAR_SYNC(1);
        load_b(0, 0, Bhi, Blo);
        do_mma(dPA, dPB, dPC, Bhi, Blo);
    }

#pragma unroll 1
    for (int t = 1; t < T_STEPS - 1; ++t) {
        const int ppr = (t - 1) & 1, ppw = t & 1;
        float dQA[4] = {0,0,0,0}, dQB[4] = {0,0,0,0}, dQC[4] = {0,0,0,0};
        {   // Q step t: sync covered by prior round's bottom work
            uint32_t Bhi[4][2], Blo[4][2];
            BAR_SYNC(2);
            load_b(1, ppr, Bhi, Blo);
            do_mma(dQA, dQB, dQC, Bhi, Blo);
        }
        {   // epilogue P(t): accP is a full round old -> latency hidden
            float2 xv = *reinterpret_cast<const float2*>(&sx[t][c0]);
            hp[0] = tanh_fast(dPA[0] + dPB[0] + dPC[0] + fmaf(wih0, xv.x, bi0));
            hp[1] = tanh_fast(dPA[1] + dPB[1] + dPC[1] + fmaf(wih0, xv.y, bi0));
            hp[2] = tanh_fast(dPA[2] + dPB[2] + dPC[2] + fmaf(wih1, xv.x, bi1));
            hp[3] = tanh_fast(dPA[3] + dPB[3] + dPC[3] + fmaf(wih1, xv.y, bi1));
            store_h(0, ppw, hp); BAR_ARRIVE(1);
        }
        {   // epilogue Q(t): fills the arriveBP -> syncBP window
            float2 xv = *reinterpret_cast<const float2*>(&sx[t][c0 + 8]);
            hq[0] = tanh_fast(dQA[0] + dQB[0] + dQC[0] + fmaf(wih0, xv.x, bi0));
            hq[1] = tanh_fast(dQA[1] + dQB[1] + dQC[1] + fmaf(wih0, xv.y, bi0));
            hq[2] = tanh_fast(dQA[2] + dQB[2] + dQC[2] + fmaf(wih1, xv.x, bi1));
            hq[3] = tanh_fast(dQA[3] + dQB[3] + dQC[3] + fmaf(wih1, xv.y, bi1));
            store_h(1, ppw, hq); BAR_ARRIVE(2);
        }
        {   // P step t+1: fills the arriveBQ -> syncBQ window across the backedge
            uint32_t Bhi[4][2], Blo[4][2];
            BAR_SYNC(1);
            load_b(0, ppw, Bhi, Blo);
            dPA[0]=dPA[1]=dPA[2]=dPA[3]=0.0f;
            dPB[0]=dPB[1]=dPB[2]=dPB[3]=0.0f;
            dPC[0]=dPC[1]=dPC[2]=dPC[3]=0.0f;
            do_mma(dPA, dPB, dPC, Bhi, Blo);
        }
    }

    // ---- final step t = T-1 = 511 ----
    {
        const int ppr = (T_STEPS - 2) & 1;   // 0
        float dQA[4] = {0,0,0,0}, dQB[4] = {0,0,0,0}, dQC[4] = {0,0,0,0};
        uint32_t Bhi[4][2], Blo[4][2];
        BAR_SYNC(2);
        load_b(1, ppr, Bhi, Blo);
        do_mma(dQA, dQB, dQC, Bhi, Blo);

        float2 xv = *reinterpret_cast<const float2*>(&sx[T_STEPS - 1][c0]);
        hp[0] = tanh_fast(dPA[0] + dPB[0] + dPC[0] + fmaf(wih0, xv.x, bi0));
        hp[1] = tanh_fast(dPA[1] + dPB[1] + dPC[1] + fmaf(wih0, xv.y, bi0));
        hp[2] = tanh_fast(dPA[2] + dPB[2] + dPC[2] + fmaf(wih1, xv.x, bi1));
        hp[3] = tanh_fast(dPA[3] + dPB[3] + dPC[3] + fmaf(wih1, xv.y, bi1));

        float2 xw = *reinterpret_cast<const float2*>(&sx[T_STEPS - 1][c0 + 8]);
        hq[0] = tanh_fast(dQA[0] + dQB[0] + dQC[0] + fmaf(wih0, xw.x, bi0));
        hq[1] = tanh_fast(dQA[1] + dQB[1] + dQC[1] + fmaf(wih0, xw.y, bi0));
        hq[2] = tanh_fast(dQA[2] + dQB[2] + dQC[2] + fmaf(wih1, xw.x, bi1));
        hq[3] = tanh_fast(dQA[3] + dQB[3] + dQC[3] + fmaf(wih1, xw.y, bi1));
    }

    // ---- FC: out[n] = sum_m fc_w[m] h[m][n] + fc_b, both groups ----
    float p0 = fmaf(fw0, hp[0], fw1 * hp[2]);   // (P, c0)
    float p1 = fmaf(fw0, hp[1], fw1 * hp[3]);   // (P, c1)
    float q0 = fmaf(fw0, hq[0], fw1 * hq[2]);   // (Q, c0+8)
    float q1 = fmaf(fw0, hq[1], fw1 * hq[3]);   // (Q, c1+8)
#pragma unroll
    for (int o = 4; o < 32; o <<= 1) {          // reduce across g-groups
        p0 += __shfl_xor_sync(0xffffffffu, p0, o);
        p1 += __shfl_xor_sync(0xffffffffu, p1, o);
        q0 += __shfl_xor_sync(0xffffffffu, q0, o);
        q1 += __shfl_xor_sync(0xffffffffu, q1, o);
    }
    if (lane < 4) {
        red[wid][c0]     = p0;  red[wid][c1]     = p1;
        red[wid][c0 + 8] = q0;  red[wid][c1 + 8] = q1;
    }
    __syncthreads();
    if (tid < NB)
        out[b0 + tid] = red[0][tid] + red[1][tid] + red[2][tid] + red[3][tid] + fc_b[0];
}

extern "C" void kernel_launch(void* const* d_in, const int* in_sizes, int n_in,
                              void* d_out, int out_size)
{
    const float* x    = (const float*)d_in[0];  // [B, T, 1]
    const float* W_ih = (const float*)d_in[1];  // [64, 1]
    const float* W_hh = (const float*)d_in[2];  // [64, 64]
    const float* b_ih = (const float*)d_in[3];  // [64]
    const float* b_hh = (const float*)d_in[4];  // [64]
    const float* fc_w = (const float*)d_in[5];  // [1, 64]
    const float* fc_b = (const float*)d_in[6];  // [1]
    float* out = (float*)d_out;                 // [B, 1]

    int B = in_sizes[0] / T_STEPS;              // I == 1
    rnn_hmma2_kernel<<<B / NB, 128>>>(x, W_ih, W_hh, b_ih, b_hh, fc_w, fc_b, out);
}

// round 12
// speedup vs baseline: 1.1983x; 1.1983x over previous
#include <cuda_runtime.h>
#include <cuda_bf16.h>
#include <cstdint>

#define T_STEPS 512
#define HID 64
#define NB 8          // batches per CTA
#define KPAD 72       // bf16 elems per h-row: 144B = 36 words -> bank+4 per row (conflict-free B frags)

__device__ __forceinline__ float tanh_fast(float x) {
    float e; asm("ex2.approx.f32 %0, %1;" : "=f"(e) : "f"(x * 2.885390082f)); // 2*log2(e)
    float r; asm("rcp.approx.f32 %0, %1;" : "=f"(r) : "f"(e + 1.0f));
    return fmaf(-2.0f, r, 1.0f);
}

// split (a,b) into packed-bf16 hi and lo parts: w = hi + lo, |w-hi-lo| ~ 2^-17 |w|
__device__ __forceinline__ void split2(float a, float b, uint32_t &uhi, uint32_t &ulo) {
    __nv_bfloat16 ah = __float2bfloat16_rn(a), bh = __float2bfloat16_rn(b);
    float ar = a - __bfloat162float(ah), br = b - __bfloat162float(bh);
    __nv_bfloat16 al = __float2bfloat16_rn(ar), bl = __float2bfloat16_rn(br);
    uhi = ((uint32_t)__bfloat16_as_ushort(bh) << 16) | __bfloat16_as_ushort(ah);
    ulo = ((uint32_t)__bfloat16_as_ushort(bl) << 16) | __bfloat16_as_ushort(al);
}

// Ampere-style bf16 MMA, fp32 accumulate: arch-neutral PTX (works on plain sm_103).
__device__ __forceinline__ void mma16816(float d[4], const uint32_t a[4], uint32_t b0, uint32_t b1) {
    asm volatile("mma.sync.aligned.m16n8k16.row.col.f32.bf16.bf16.f32 "
        "{%0,%1,%2,%3}, {%4,%5,%6,%7}, {%8,%9}, {%0,%1,%2,%3};"
        : "+f"(d[0]), "+f"(d[1]), "+f"(d[2]), "+f"(d[3])
        : "r"(a[0]), "r"(a[1]), "r"(a[2]), "r"(a[3]), "r"(b0), "r"(b1));
}

// R10 base (155.8us) + ONE change: 12 INDEPENDENT accumulators (was 3 chains of
// depth 4). All 12 HMMAs issue back-to-back; exposed MMA latency drops from ~4x
// to ~1x. Epilogue sums the 12 partials in a tree (fma-pipe, overlappable).
__global__ void __launch_bounds__(128, 2)
rnn_hmma_kernel(const float* __restrict__ x,
                const float* __restrict__ W_ih,
                const float* __restrict__ W_hh,
                const float* __restrict__ b_ih,
                const float* __restrict__ b_hh,
                const float* __restrict__ fc_w,
                const float* __restrict__ fc_b,
                float* __restrict__ out)
{
    __shared__ __align__(16) float sx[T_STEPS][NB];                 // x transposed [t][n], 16KB
    __shared__ __align__(16) __nv_bfloat16 hbuf[2][2][NB][KPAD];    // [pingpong][split][n][k]
    __shared__ float red[4][NB];

    const int tid  = threadIdx.x;
    const int lane = tid & 31, wid = tid >> 5;
    const int g = lane >> 2, q = lane & 3;       // fragment coords
    const int mb = wid * 16;
    const int r0 = mb + g, r1 = mb + g + 8;      // this thread's two M rows
    const int c0 = 2 * q, c1 = 2 * q + 1;        // this thread's two N cols (batches)
    const int b0 = blockIdx.x * NB;

    // ---- loop-invariant A fragments: W_hh rows r0/r1, hi+lo bf16 splits (32 regs) ----
    uint32_t Ahi[4][4], Alo[4][4];
#pragma unroll
    for (int kt = 0; kt < 4; ++kt) {
        int kb = kt * 16 + 2 * q;
        split2(W_hh[r0 * HID + kb],     W_hh[r0 * HID + kb + 1],     Ahi[kt][0], Alo[kt][0]);
        split2(W_hh[r1 * HID + kb],     W_hh[r1 * HID + kb + 1],     Ahi[kt][1], Alo[kt][1]);
        split2(W_hh[r0 * HID + kb + 8], W_hh[r0 * HID + kb + 9],     Ahi[kt][2], Alo[kt][2]);
        split2(W_hh[r1 * HID + kb + 8], W_hh[r1 * HID + kb + 9],     Ahi[kt][3], Alo[kt][3]);
    }

    const float wih0 = W_ih[r0],             wih1 = W_ih[r1];
    const float bi0  = b_ih[r0] + b_hh[r0],  bi1  = b_ih[r1] + b_hh[r1];
    const float fw0  = fc_w[r0],             fw1  = fc_w[r1];

    // ---- stage x transposed: sx[t][n]  (I=1 -> each batch is 512 contiguous floats) ----
    {
        const float4* xg = reinterpret_cast<const float4*>(x + (size_t)b0 * T_STEPS);
        for (int i = tid; i < NB * (T_STEPS / 4); i += 128) {
            int bb = i >> 7, t4 = (i & 127) * 4;
            float4 v = xg[(i >> 7) * 128 + (i & 127)];
            sx[t4 + 0][bb] = v.x; sx[t4 + 1][bb] = v.y;
            sx[t4 + 2][bb] = v.z; sx[t4 + 3][bb] = v.w;
        }
    }
    __syncthreads();

    // ---- t=0: h(0) = tanh(x*W_ih + bias) -> write split h into hbuf[1] ----
    float h0, h1, h2, h3;
    {
        float xa = sx[0][c0], xb = sx[0][c1];
        h0 = tanh_fast(fmaf(wih0, xa, bi0));  h1 = tanh_fast(fmaf(wih0, xb, bi0));
        h2 = tanh_fast(fmaf(wih1, xa, bi1));  h3 = tanh_fast(fmaf(wih1, xb, bi1));
    }
    {
        float hv[4] = {h0, h1, h2, h3};
        int   nn[4] = {c0, c1, c0, c1};
        int   mm[4] = {r0, r0, r1, r1};
#pragma unroll
        for (int i = 0; i < 4; ++i) {
            __nv_bfloat16 vhi = __float2bfloat16_rn(hv[i]);
            __nv_bfloat16 vlo = __float2bfloat16_rn(hv[i] - __bfloat162float(vhi));
            hbuf[1][0][nn[i]][mm[i]] = vhi;
            hbuf[1][1][nn[i]][mm[i]] = vlo;
        }
    }
    __syncthreads();

    // ---- recurrence: iteration t reads hbuf[t&1], writes hbuf[(t+1)&1] ----
#pragma unroll 1
    for (int t = 1; t < T_STEPS; ++t) {
        const int cur = t & 1, nxt = cur ^ 1;

        uint32_t Bhi[4][2], Blo[4][2];
#pragma unroll
        for (int kt = 0; kt < 4; ++kt) {
            int kb = kt * 16 + 2 * q;
            Bhi[kt][0] = *reinterpret_cast<const uint32_t*>(&hbuf[cur][0][g][kb]);
            Bhi[kt][1] = *reinterpret_cast<const uint32_t*>(&hbuf[cur][0][g][kb + 8]);
            Blo[kt][0] = *reinterpret_cast<const uint32_t*>(&hbuf[cur][1][g][kb]);
            Blo[kt][1] = *reinterpret_cast<const uint32_t*>(&hbuf[cur][1][g][kb + 8]);
        }

        // 12 INDEPENDENT accumulators: no MMA->MMA dependencies at all.
        float dd[12][4];
#pragma unroll
        for (int j = 0; j < 12; ++j) { dd[j][0] = dd[j][1] = dd[j][2] = dd[j][3] = 0.0f; }
#pragma unroll
        for (int kt = 0; kt < 4; ++kt) {
            mma16816(dd[kt],     Ahi[kt], Bhi[kt][0], Bhi[kt][1]);   // Whi * h_hi
            mma16816(dd[4 + kt], Ahi[kt], Blo[kt][0], Blo[kt][1]);   // Whi * h_lo
            mma16816(dd[8 + kt], Alo[kt], Bhi[kt][0], Bhi[kt][1]);   // Wlo * h_hi
        }

        // Tree-sum the 12 partials per output element (keeps 4 independent chains).
        float s[4];
#pragma unroll
        for (int i = 0; i < 4; ++i) {
            float p01 = dd[0][i] + dd[1][i],  p23 = dd[2][i]  + dd[3][i];
            float p45 = dd[4][i] + dd[5][i],  p67 = dd[6][i]  + dd[7][i];
            float p89 = dd[8][i] + dd[9][i],  pab = dd[10][i] + dd[11][i];
            s[i] = ((p01 + p23) + (p45 + p67)) + (p89 + pab);
        }

        float2 xv = *reinterpret_cast<const float2*>(&sx[t][c0]);
        h0 = tanh_fast(s[0] + fmaf(wih0, xv.x, bi0));  // (r0, c0)
        h1 = tanh_fast(s[1] + fmaf(wih0, xv.y, bi0));  // (r0, c1)
        h2 = tanh_fast(s[2] + fmaf(wih1, xv.x, bi1));  // (r1, c0)
        h3 = tanh_fast(s[3] + fmaf(wih1, xv.y, bi1));  // (r1, c1)

        {
            float hv[4] = {h0, h1, h2, h3};
            int   nn[4] = {c0, c1, c0, c1};
            int   mm[4] = {r0, r0, r1, r1};
#pragma unroll
            for (int i = 0; i < 4; ++i) {
                __nv_bfloat16 vhi = __float2bfloat16_rn(hv[i]);
                __nv_bfloat16 vlo = __float2bfloat16_rn(hv[i] - __bfloat162float(vhi));
                hbuf[nxt][0][nn[i]][mm[i]] = vhi;
                hbuf[nxt][1][nn[i]][mm[i]] = vlo;
            }
        }
        __syncthreads();
    }

    // ---- FC on h(T-1) held in regs: out[n] = sum_m fc_w[m] h[m][n] + fc_b ----
    float p0 = fmaf(fw0, h0, fw1 * h2);   // n = c0
    float p1 = fmaf(fw0, h1, fw1 * h3);   // n = c1
#pragma unroll
    for (int o = 4; o < 32; o <<= 1) {    // reduce over g-groups (lanes with same q)
        p0 += __shfl_xor_sync(0xffffffffu, p0, o);
        p1 += __shfl_xor_sync(0xffffffffu, p1, o);
    }
    if (lane < 4) { red[wid][c0] = p0; red[wid][c1] = p1; }
    __syncthreads();
    if (tid < NB)
        out[b0 + tid] = red[0][tid] + red[1][tid] + red[2][tid] + red[3][tid] + fc_b[0];
}

extern "C" void kernel_launch(void* const* d_in, const int* in_sizes, int n_in,
                              void* d_out, int out_size)
{
    const float* x    = (const float*)d_in[0];  // [B, T, 1]
    const float* W_ih = (const float*)d_in[1];  // [64, 1]
    const float* W_hh = (const float*)d_in[2];  // [64, 64]
    const float* b_ih = (const float*)d_in[3];  // [64]
    const float* b_hh = (const float*)d_in[4];  // [64]
    const float* fc_w = (const float*)d_in[5];  // [1, 64]
    const float* fc_b = (const float*)d_in[6];  // [1]
    float* out = (float*)d_out;                 // [B, 1]

    int B = in_sizes[0] / T_STEPS;              // I == 1
    rnn_hmma_kernel<<<B / NB, 128>>>(x, W_ih, W_hh, b_ih, b_hh, fc_w, fc_b, out);
}

// round 13
// speedup vs baseline: 1.2992x; 1.0842x over previous
#include <cuda_runtime.h>
#include <cuda_bf16.h>
#include <cstdint>

#define T_STEPS 512
#define HID 64
#define NB 8          // batches per CTA
#define KPAD 72       // bf16 elems per h-row: 144B = 36 words -> bank+4 per row (conflict-free B frags)

__device__ __forceinline__ float tanh_fast(float x) {
    float e; asm("ex2.approx.f32 %0, %1;" : "=f"(e) : "f"(x * 2.885390082f)); // 2*log2(e)
    float r; asm("rcp.approx.f32 %0, %1;" : "=f"(r) : "f"(e + 1.0f));
    return fmaf(-2.0f, r, 1.0f);
}

// split for W (loop-invariant; use accurate cvt.rn): w = hi + lo packed bf16x2
__device__ __forceinline__ void split2(float a, float b, uint32_t &uhi, uint32_t &ulo) {
    __nv_bfloat16 ah = __float2bfloat16_rn(a), bh = __float2bfloat16_rn(b);
    float ar = a - __bfloat162float(ah), br = b - __bfloat162float(bh);
    __nv_bfloat16 al = __float2bfloat16_rn(ar), bl = __float2bfloat16_rn(br);
    uhi = ((uint32_t)__bfloat16_as_ushort(bh) << 16) | __bfloat16_as_ushort(ah);
    ulo = ((uint32_t)__bfloat16_as_ushort(bl) << 16) | __bfloat16_as_ushort(al);
}

// Ampere-style bf16 MMA, fp32 accumulate: arch-neutral PTX (works on plain sm_103).
__device__ __forceinline__ void mma16816(float d[4], const uint32_t a[4], uint32_t b0, uint32_t b1) {
    asm volatile("mma.sync.aligned.m16n8k16.row.col.f32.bf16.bf16.f32 "
        "{%0,%1,%2,%3}, {%4,%5,%6,%7}, {%8,%9}, {%0,%1,%2,%3};"
        : "+f"(d[0]), "+f"(d[1]), "+f"(d[2]), "+f"(d[3])
        : "r"(a[0]), "r"(a[1]), "r"(a[2]), "r"(a[3]), "r"(b0), "r"(b1));
}

// R10 base + serial-chain cuts:
//  (1) truncation-based h split (lat-4 ALU ops instead of two dependent ~20-cyc cvts):
//      hi = bits & 0xFFFF0000 (exact h = hi + lo in fp32), lo_bf16 = top16(lo);
//      residual <= 2^-16 |h| — same order as cvt.rn split.
//  (2) xp folded into accumulator init (no epilogue adds for xp, x load off chain).
__global__ void __launch_bounds__(128, 2)
rnn_hmma_kernel(const float* __restrict__ x,
                const float* __restrict__ W_ih,
                const float* __restrict__ W_hh,
                const float* __restrict__ b_ih,
                const float* __restrict__ b_hh,
                const float* __restrict__ fc_w,
                const float* __restrict__ fc_b,
                float* __restrict__ out)
{
    __shared__ __align__(16) float sx[T_STEPS][NB];                 // x transposed [t][n], 16KB
    __shared__ __align__(16) __nv_bfloat16 hbuf[2][2][NB][KPAD];    // [pingpong][split][n][k]
    __shared__ float red[4][NB];

    const int tid  = threadIdx.x;
    const int lane = tid & 31, wid = tid >> 5;
    const int g = lane >> 2, q = lane & 3;       // fragment coords
    const int mb = wid * 16;
    const int r0 = mb + g, r1 = mb + g + 8;      // this thread's two M rows
    const int c0 = 2 * q, c1 = 2 * q + 1;        // this thread's two N cols (batches)
    const int b0 = blockIdx.x * NB;

    // ---- loop-invariant A fragments: W_hh rows r0/r1, hi+lo bf16 splits (32 regs) ----
    uint32_t Ahi[4][4], Alo[4][4];
#pragma unroll
    for (int kt = 0; kt < 4; ++kt) {
        int kb = kt * 16 + 2 * q;
        split2(W_hh[r0 * HID + kb],     W_hh[r0 * HID + kb + 1],     Ahi[kt][0], Alo[kt][0]);
        split2(W_hh[r1 * HID + kb],     W_hh[r1 * HID + kb + 1],     Ahi[kt][1], Alo[kt][1]);
        split2(W_hh[r0 * HID + kb + 8], W_hh[r0 * HID + kb + 9],     Ahi[kt][2], Alo[kt][2]);
        split2(W_hh[r1 * HID + kb + 8], W_hh[r1 * HID + kb + 9],     Ahi[kt][3], Alo[kt][3]);
    }

    const float wih0 = W_ih[r0],             wih1 = W_ih[r1];
    const float bi0  = b_ih[r0] + b_hh[r0],  bi1  = b_ih[r1] + b_hh[r1];
    const float fw0  = fc_w[r0],             fw1  = fc_w[r1];

    // ---- stage x transposed: sx[t][n]  (I=1 -> each batch is 512 contiguous floats) ----
    {
        const float4* xg = reinterpret_cast<const float4*>(x + (size_t)b0 * T_STEPS);
        for (int i = tid; i < NB * (T_STEPS / 4); i += 128) {
            int bb = i >> 7, t4 = (i & 127) * 4;
            float4 v = xg[(i >> 7) * 128 + (i & 127)];
            sx[t4 + 0][bb] = v.x; sx[t4 + 1][bb] = v.y;
            sx[t4 + 2][bb] = v.z; sx[t4 + 3][bb] = v.w;
        }
    }
    __syncthreads();

    // fast trunc split + store: hi = top16(h), lo = h - hi (exact), lo16 = top16(lo)
    auto store_h = [&](int pp, const float hv[4]) {
        const int nn[4] = {c0, c1, c0, c1};
        const int mm[4] = {r0, r0, r1, r1};
#pragma unroll
        for (int i = 0; i < 4; ++i) {
            uint32_t u = __float_as_uint(hv[i]);
            float lo = hv[i] - __uint_as_float(u & 0xFFFF0000u);
            uint32_t ul = __float_as_uint(lo);
            *reinterpret_cast<unsigned short*>(&hbuf[pp][0][nn[i]][mm[i]]) = (unsigned short)(u >> 16);
            *reinterpret_cast<unsigned short*>(&hbuf[pp][1][nn[i]][mm[i]]) = (unsigned short)(ul >> 16);
        }
    };

    // ---- t=0: h(0) = tanh(x*W_ih + bias) -> hbuf[1] ----
    float h0, h1, h2, h3;
    {
        float xa = sx[0][c0], xb = sx[0][c1];
        h0 = tanh_fast(fmaf(wih0, xa, bi0));  h1 = tanh_fast(fmaf(wih0, xb, bi0));
        h2 = tanh_fast(fmaf(wih1, xa, bi1));  h3 = tanh_fast(fmaf(wih1, xb, bi1));
        float hv[4] = {h0, h1, h2, h3};
        store_h(1, hv);
    }
    __syncthreads();

    // ---- recurrence: iteration t reads hbuf[t&1], writes hbuf[(t+1)&1] ----
#pragma unroll 1
    for (int t = 1; t < T_STEPS; ++t) {
        const int cur = t & 1, nxt = cur ^ 1;

        // init dA chain with xp (off the critical chain; x is read-only smem)
        float2 xv = *reinterpret_cast<const float2*>(&sx[t][c0]);
        float dA[4] = { fmaf(wih0, xv.x, bi0), fmaf(wih0, xv.y, bi0),
                        fmaf(wih1, xv.x, bi1), fmaf(wih1, xv.y, bi1) };
        float dB[4] = {0, 0, 0, 0}, dC[4] = {0, 0, 0, 0};

        uint32_t Bhi[4][2], Blo[4][2];
#pragma unroll
        for (int kt = 0; kt < 4; ++kt) {
            int kb = kt * 16 + 2 * q;
            Bhi[kt][0] = *reinterpret_cast<const uint32_t*>(&hbuf[cur][0][g][kb]);
            Bhi[kt][1] = *reinterpret_cast<const uint32_t*>(&hbuf[cur][0][g][kb + 8]);
            Blo[kt][0] = *reinterpret_cast<const uint32_t*>(&hbuf[cur][1][g][kb]);
            Blo[kt][1] = *reinterpret_cast<const uint32_t*>(&hbuf[cur][1][g][kb + 8]);
        }
#pragma unroll
        for (int kt = 0; kt < 4; ++kt) {
            mma16816(dA, Ahi[kt], Bhi[kt][0], Bhi[kt][1]);   // Whi * h_hi  (+xp init)
            mma16816(dB, Ahi[kt], Blo[kt][0], Blo[kt][1]);   // Whi * h_lo
            mma16816(dC, Alo[kt], Bhi[kt][0], Bhi[kt][1]);   // Wlo * h_hi
        }

        h0 = tanh_fast(dA[0] + (dB[0] + dC[0]));  // (r0, c0)
        h1 = tanh_fast(dA[1] + (dB[1] + dC[1]));  // (r0, c1)
        h2 = tanh_fast(dA[2] + (dB[2] + dC[2]));  // (r1, c0)
        h3 = tanh_fast(dA[3] + (dB[3] + dC[3]));  // (r1, c1)

        float hv[4] = {h0, h1, h2, h3};
        store_h(nxt, hv);
        __syncthreads();
    }

    // ---- FC on h(T-1) held in regs: out[n] = sum_m fc_w[m] h[m][n] + fc_b ----
    float p0 = fmaf(fw0, h0, fw1 * h2);   // n = c0
    float p1 = fmaf(fw0, h1, fw1 * h3);   // n = c1
#pragma unroll
    for (int o = 4; o < 32; o <<= 1) {    // reduce over g-groups (lanes with same q)
        p0 += __shfl_xor_sync(0xffffffffu, p0, o);
        p1 += __shfl_xor_sync(0xffffffffu, p1, o);
    }
    if (lane < 4) { red[wid][c0] = p0; red[wid][c1] = p1; }
    __syncthreads();
    if (tid < NB)
        out[b0 + tid] = red[0][tid] + red[1][tid] + red[2][tid] + red[3][tid] + fc_b[0];
}

extern "C" void kernel_launch(void* const* d_in, const int* in_sizes, int n_in,
                              void* d_out, int out_size)
{
    const float* x    = (const float*)d_in[0];  // [B, T, 1]
    const float* W_ih = (const float*)d_in[1];  // [64, 1]
    const float* W_hh = (const float*)d_in[2];  // [64, 64]
    const float* b_ih = (const float*)d_in[3];  // [64]
    const float* b_hh = (const float*)d_in[4];  // [64]
    const float* fc_w = (const float*)d_in[5];  // [1, 64]
    const float* fc_b = (const float*)d_in[6];  // [1]
    float* out = (float*)d_out;                 // [B, 1]

    int B = in_sizes[0] / T_STEPS;              // I == 1
    rnn_hmma_kernel<<<B / NB, 128>>>(x, W_ih, W_hh, b_ih, b_hh, fc_w, fc_b, out);
}